// round 11
// baseline (speedup 1.0000x reference)
#include <cuda_runtime.h>
#include <cstdint>
#include <cstddef>

#define TT 512
#define BB 16
#define EE 1024
#define HH 512
#define G3 1536
#define SENT 0x7FC00001u

// pre-gate scratch [d][t][col][b]
__device__ float g_preg[(size_t)2 * TT * G3 * BB];
// tf32-pre-rounded h staging [d][t][k][b]; sentinel-filled each launch
__device__ float g_hstage[(size_t)2 * TT * HH * BB];

static __device__ __forceinline__ uint32_t f2tf(float f) {
    uint32_t r; asm("cvt.rna.tf32.f32 %0, %1;" : "=r"(r) : "f"(f)); return r;
}
static __device__ __forceinline__ float f2tff(float f) { return __uint_as_float(f2tf(f)); }
static __device__ __forceinline__ float rcpa(float x) {
    float r; asm("rcp.approx.f32 %0, %1;" : "=f"(r) : "f"(x)); return r;
}

static __device__ __forceinline__ void mma8(float& d0, float& d1, float& d2, float& d3,
                                            uint32_t a0, uint32_t a1, uint32_t a2, uint32_t a3,
                                            uint32_t b0, uint32_t b1) {
    asm volatile(
        "mma.sync.aligned.m16n8k8.row.col.f32.tf32.tf32.f32 "
        "{%0,%1,%2,%3}, {%4,%5,%6,%7}, {%8,%9}, {%0,%1,%2,%3};"
        : "+f"(d0), "+f"(d1), "+f"(d2), "+f"(d3)
        : "r"(a0), "r"(a1), "r"(a2), "r"(a3), "r"(b0), "r"(b1));
}

// L1-bypassing (gpu-scope) loads/stores for the producer-consumer handoff
static __device__ __forceinline__ float4 ld_rlx4(const float* p) {
    float4 v;
    asm volatile("ld.relaxed.gpu.global.v4.f32 {%0,%1,%2,%3}, [%4];"
                 : "=f"(v.x), "=f"(v.y), "=f"(v.z), "=f"(v.w) : "l"(p) : "memory");
    return v;
}
static __device__ __forceinline__ void st_rlx(float* p, float v) {
    asm volatile("st.relaxed.gpu.global.f32 [%0], %1;" :: "l"(p), "f"(v) : "memory");
}
static __device__ __forceinline__ bool has_sent(float4 v) {
    return (__float_as_uint(v.x) == SENT) | (__float_as_uint(v.y) == SENT) |
           (__float_as_uint(v.z) == SENT) | (__float_as_uint(v.w) == SENT);
}

// fill g_hstage with the sentinel pattern (runs first, every launch)
__global__ void fill_sentinel_kernel() {
    const size_t n4 = (size_t)2 * TT * HH * BB / 4;
    uint4 s = make_uint4(SENT, SENT, SENT, SENT);
    uint4* p = reinterpret_cast<uint4*>(g_hstage);
    for (size_t i = blockIdx.x * (size_t)blockDim.x + threadIdx.x; i < n4;
         i += (size_t)gridDim.x * blockDim.x)
        p[i] = s;
}

// ---------------------------------------------------------------------------
// Phase 1: pre-gates = x @ W_x^T + bias, both directions (tf32 mma GEMM).
// M = 8192, N = 1536, K = 1024. CTA tile 128x128x32, 8 warps, warp 64x32.
// ---------------------------------------------------------------------------
__global__ __launch_bounds__(256) void pregemm_kernel(
    const float* __restrict__ x,
    const float* __restrict__ wf, const float* __restrict__ bf,
    const float* __restrict__ wb, const float* __restrict__ bb) {
    const int d = blockIdx.z;
    const float* __restrict__ w    = d ? wb : wf;
    const float* __restrict__ bias = d ? bb : bf;
    const int row0 = blockIdx.y * 128;
    const int col0 = blockIdx.x * 128;

    __shared__ float As[128][36];
    __shared__ float Bs[128][36];

    const int tid = threadIdx.x;
    const int lane = tid & 31, wid = tid >> 5;
    const int wm = wid >> 2, wn = wid & 3;
    const int g = lane >> 2, t4 = lane & 3;

    float acc[4][4][4];
#pragma unroll
    for (int i = 0; i < 4; i++)
#pragma unroll
        for (int j = 0; j < 4; j++)
#pragma unroll
            for (int r = 0; r < 4; r++) acc[i][j][r] = 0.f;

    for (int k0 = 0; k0 < EE; k0 += 32) {
#pragma unroll
        for (int i = 0; i < 4; i++) {
            int idx = tid + i * 256;
            int m = idx >> 3, kq = idx & 7;
            int row = row0 + m;
            int t = row >> 4, b = row & 15;
            float4 v = *reinterpret_cast<const float4*>(
                x + (size_t)(b * TT + t) * EE + k0 + kq * 4);
            float4 o = make_float4(f2tff(v.x), f2tff(v.y), f2tff(v.z), f2tff(v.w));
            *reinterpret_cast<float4*>(&As[m][kq * 4]) = o;
        }
#pragma unroll
        for (int i = 0; i < 4; i++) {
            int idx = tid + i * 256;
            int n = idx >> 3, kq = idx & 7;
            float4 v = *reinterpret_cast<const float4*>(
                w + (size_t)(col0 + n) * G3 + k0 + kq * 4);
            float4 o = make_float4(f2tff(v.x), f2tff(v.y), f2tff(v.z), f2tff(v.w));
            *reinterpret_cast<float4*>(&Bs[n][kq * 4]) = o;
        }
        __syncthreads();

#pragma unroll
        for (int kt = 0; kt < 4; kt++) {
            int k = kt * 8;
            uint32_t a[4][4];
#pragma unroll
            for (int mt = 0; mt < 4; mt++) {
                int mb = wm * 64 + mt * 16;
                a[mt][0] = __float_as_uint(As[mb + g][k + t4]);
                a[mt][1] = __float_as_uint(As[mb + g + 8][k + t4]);
                a[mt][2] = __float_as_uint(As[mb + g][k + 4 + t4]);
                a[mt][3] = __float_as_uint(As[mb + g + 8][k + 4 + t4]);
            }
#pragma unroll
            for (int nt = 0; nt < 4; nt++) {
                int nb = wn * 32 + nt * 8;
                uint32_t b0 = __float_as_uint(Bs[nb + g][k + t4]);
                uint32_t b1 = __float_as_uint(Bs[nb + g][k + 4 + t4]);
#pragma unroll
                for (int mt = 0; mt < 4; mt++)
                    mma8(acc[mt][nt][0], acc[mt][nt][1], acc[mt][nt][2], acc[mt][nt][3],
                         a[mt][0], a[mt][1], a[mt][2], a[mt][3], b0, b1);
            }
        }
        __syncthreads();
    }

#pragma unroll
    for (int mt = 0; mt < 4; mt++) {
        int rowb = row0 + wm * 64 + mt * 16 + g;
#pragma unroll
        for (int nt = 0; nt < 4; nt++) {
            int colb = col0 + wn * 32 + nt * 8 + 2 * t4;
#pragma unroll
            for (int r = 0; r < 4; r++) {
                int row = rowb + ((r >= 2) ? 8 : 0);
                int col = colb + (r & 1);
                int t = row >> 4, b = row & 15;
                float v = acc[mt][nt][r] + __ldg(bias + col);
                g_preg[(((size_t)d * TT + t) * G3 + col) * BB + b] = v;
            }
        }
    }
}

// ---------------------------------------------------------------------------
// Phase 2: persistent recurrence — R10 structure (warp-owned 128B hst lines,
// coalesced single-wavefront publish, deferred out) with ONE change: the
// detect-then-verify poll becomes a merged 8x v4 poll — the loads that
// detect arrival ARE the data loads, folding handoff into one L2 RT.
// ---------------------------------------------------------------------------
#define WPAD 516
#define RPAD 25

__global__ __launch_bounds__(256) void recur_kernel(
    const float* __restrict__ wf, const float* __restrict__ wb,
    const float* __restrict__ h0f, const float* __restrict__ h0b,
    const float* __restrict__ c0f, const float* __restrict__ c0b,
    float* __restrict__ out) {
    extern __shared__ float sm[];
    float* hsm = sm;                       // 16 x WPAD  (h_{t-1} [b][k])
    float* red = sm + 16 * WPAD;           // 2 x 8 x 16 x RPAD (parity)
    float* hT  = red + 2 * 8 * 16 * RPAD;  // 2 x 8 x 20 parity h buffer

    const int d   = (int)blockIdx.x >> 6;
    const int grp = (int)blockIdx.x & 63;
    const int n0  = grp * 8;
    const float* __restrict__ w  = d ? wb : wf;
    const float* __restrict__ h0 = d ? h0b : h0f;
    const float* __restrict__ c0 = d ? c0b : c0f;
    const float* __restrict__ preg = g_preg + (size_t)d * TT * G3 * BB;
    float* __restrict__ hst = g_hstage + (size_t)d * TT * HH * BB;

    const int tid = threadIdx.x, lane = tid & 31, wid = tid >> 5;
    const int g = lane >> 2, t4 = lane & 3;
    // epilogue mapping: warp w owns cols 2w,2w+1 x all 16 batches
    const int eb = tid & 15, en = (tid >> 4) & 7;
    // out-writeback mapping (coalesced): consecutive lanes -> consecutive cols
    const int en2 = tid & 7, eb2 = (tid >> 3) & 15;
    const bool epi = tid < 128;
    const int kbase = wid * 64;       // this warp's K slice
    const int k2 = tid * 2;           // the 2 k-columns I stage (one 128B line)

    // Preload this thread's W_h B-fragments into registers (tf32).
    float breg[8][3][2];
#pragma unroll
    for (int nt = 0; nt < 3; nt++) {
        const float* wr = w + (size_t)(nt * 512 + n0 + g) * G3 + 1024;
#pragma unroll
        for (int kt = 0; kt < 8; kt++) {
            int col = kbase + kt * 8;
            breg[kt][nt][0] = f2tff(__ldg(wr + col + t4));
            breg[kt][nt][1] = f2tff(__ldg(wr + col + 4 + t4));
        }
    }
    float c = epi ? c0[n0 + en] : 0.f;  // cell state in a register

    // step-0 h: broadcast h0 over batch into my 2 columns
    {
        float2 o = make_float2(f2tff(h0[k2]), f2tff(h0[k2 + 1]));
#pragma unroll
        for (int b = 0; b < 16; b++)
            *reinterpret_cast<float2*>(&hsm[b * WPAD + k2]) = o;
    }
    __syncthreads();

    for (int s = 0; s < TT; s++) {
        const int tt = d ? (TT - 1 - s) : s;
        const int par = s & 1;
        float* redp = red + par * (8 * 16 * RPAD);

        // pre-gate prefetch (independent; overlaps the poll below)
        float pgi = 0.f, pgj = 0.f, pgo = 0.f;
        if (epi) {
            pgi = __ldg(preg + ((size_t)tt * G3 + (n0 + en)) * BB + eb);
            pgj = __ldg(preg + ((size_t)tt * G3 + (512 + n0 + en)) * BB + eb);
            pgo = __ldg(preg + ((size_t)tt * G3 + (1024 + n0 + en)) * BB + eb);
        }

        if (s > 0) {
            // merged poll: all 8 v4 loads in flight each iteration; the
            // detecting loads ARE the data loads (one L2 RT total). Safe for
            // any sector-arrival order: loop until no word is the sentinel.
            const int tp = d ? (tt + 1) : (tt - 1);
            const float* sp = hst + ((size_t)tp * HH + k2) * BB;
            float4 v[8];
            for (;;) {
                bool bad = false;
#pragma unroll
                for (int q = 0; q < 8; q++) {
                    v[q] = ld_rlx4(sp + q * 4);
                    bad |= has_sent(v[q]);
                }
                if (!bad) break;
            }
            // transpose: v[0..3] = col k2 (b 0..15), v[4..7] = col k2+1
#pragma unroll
            for (int q = 0; q < 4; q++) {
                const float* a = &v[q].x;
                const float* bq = &v[4 + q].x;
#pragma unroll
                for (int r = 0; r < 4; r++)
                    *reinterpret_cast<float2*>(&hsm[(q * 4 + r) * WPAD + k2]) =
                        make_float2(a[r], bq[r]);
            }
        }
        __syncwarp();  // my warp's staging visible to my warp's mma

        // per-warp mma on its own K slice: A from SMEM, B from registers
        float acc[3][4];
#pragma unroll
        for (int nt = 0; nt < 3; nt++)
#pragma unroll
            for (int r = 0; r < 4; r++) acc[nt][r] = 0.f;

#pragma unroll
        for (int kt = 0; kt < 8; kt++) {
            int k = kbase + kt * 8;
            uint32_t a0 = __float_as_uint(hsm[g * WPAD + k + t4]);
            uint32_t a1 = __float_as_uint(hsm[(g + 8) * WPAD + k + t4]);
            uint32_t a2 = __float_as_uint(hsm[g * WPAD + k + 4 + t4]);
            uint32_t a3 = __float_as_uint(hsm[(g + 8) * WPAD + k + 4 + t4]);
#pragma unroll
            for (int nt = 0; nt < 3; nt++)
                mma8(acc[nt][0], acc[nt][1], acc[nt][2], acc[nt][3],
                     a0, a1, a2, a3,
                     __float_as_uint(breg[kt][nt][0]),
                     __float_as_uint(breg[kt][nt][1]));
        }

        // cross-warp K reduction via SMEM (parity-buffered)
        float* rw = redp + wid * 16 * RPAD;
#pragma unroll
        for (int nt = 0; nt < 3; nt++) {
            int rl = nt * 8 + 2 * t4;
            rw[g * RPAD + rl]           = acc[nt][0];
            rw[g * RPAD + rl + 1]       = acc[nt][1];
            rw[(g + 8) * RPAD + rl]     = acc[nt][2];
            rw[(g + 8) * RPAD + rl + 1] = acc[nt][3];
        }
        __syncthreads();  // the single CTA-wide barrier per step

        if (epi) {
            float si = pgi, sj = pgj, so = pgo;
#pragma unroll
            for (int wq = 0; wq < 8; wq++) {
                const float* rr = redp + (wq * 16 + eb) * RPAD;
                si += rr[en];
                sj += rr[8 + en];
                so += rr[16 + en];
            }
            // fast MUFU-only gates (err ~1e-6)
            float ig = rcpa(1.f + __expf(-si));
            float tj = 1.f - 2.f * rcpa(1.f + __expf(2.f * sj));
            c = (1.f - ig) * c + ig * tj;                       // coupled gate
            float tc = 1.f - 2.f * rcpa(1.f + __expf(2.f * c));
            float h = tc * rcpa(1.f + __expf(-so));

            // publish FIRST: my warp owns one full 128B hst line -> one
            // coalesced wavefront, atomic-ish arrival at L2
            st_rlx(hst + ((size_t)tt * HH + n0 + en) * BB + eb, f2tff(h));
            // stash full-precision h for the deferred out write
            hT[par * 160 + en * 20 + eb] = h;

            // deferred coalesced out write for step s-1 (off critical path)
            if (s > 0) {
                const float* hTp = hT + (par ^ 1) * 160;
                const int tprev = d ? (TT - s) : (s - 1);
                out[(size_t)(eb2 * TT + tprev) * 1024 + d * 512 + n0 + en2] =
                    hTp[en2 * 20 + eb2];
            }
        }
    }

    // flush the final step's out values
    __syncthreads();
    if (epi) {
        const float* hTp = hT + ((TT - 1) & 1) * 160;
        const int tlast = d ? 0 : (TT - 1);
        out[(size_t)(eb2 * TT + tlast) * 1024 + d * 512 + n0 + en2] =
            hTp[en2 * 20 + eb2];
    }
}

extern "C" void kernel_launch(void* const* d_in, const int* in_sizes, int n_in,
                              void* d_out, int out_size) {
    (void)in_sizes; (void)n_in; (void)out_size;
    const float* x   = (const float*)d_in[0];
    const float* wf  = (const float*)d_in[1];
    const float* bf  = (const float*)d_in[2];
    const float* wb  = (const float*)d_in[3];
    const float* bb  = (const float*)d_in[4];
    const float* h0f = (const float*)d_in[5];
    const float* h0b = (const float*)d_in[6];
    const float* c0f = (const float*)d_in[7];
    const float* c0b = (const float*)d_in[8];
    float* out = (float*)d_out;

    const int rsm_bytes = (16 * WPAD + 2 * 8 * 16 * RPAD + 2 * 160) * 4;  // 59904
    cudaFuncSetAttribute(recur_kernel, cudaFuncAttributeMaxDynamicSharedMemorySize,
                         rsm_bytes);

    fill_sentinel_kernel<<<512, 256>>>();
    dim3 g1(G3 / 128, (TT * BB) / 128, 2);
    pregemm_kernel<<<g1, 256>>>(x, wf, bf, wb, bb);
    recur_kernel<<<128, 256, rsm_bytes>>>(wf, wb, h0f, h0b, c0f, c0b, out);
}

// round 12
// speedup vs baseline: 1.1398x; 1.1398x over previous
#include <cuda_runtime.h>
#include <cstdint>
#include <cstddef>

#define TT 512
#define BB 16
#define EE 1024
#define HH 512
#define G3 1536
#define SENT 0x7FC00001u

// pre-gate scratch [d][t][col][b]
__device__ float g_preg[(size_t)2 * TT * G3 * BB];
// tf32-pre-rounded h staging [d][t][k][b]; sentinel-filled each launch
__device__ float g_hstage[(size_t)2 * TT * HH * BB];

static __device__ __forceinline__ uint32_t f2tf(float f) {
    uint32_t r; asm("cvt.rna.tf32.f32 %0, %1;" : "=r"(r) : "f"(f)); return r;
}
static __device__ __forceinline__ float f2tff(float f) { return __uint_as_float(f2tf(f)); }
static __device__ __forceinline__ float rcpa(float x) {
    float r; asm("rcp.approx.f32 %0, %1;" : "=f"(r) : "f"(x)); return r;
}

static __device__ __forceinline__ void mma8(float& d0, float& d1, float& d2, float& d3,
                                            uint32_t a0, uint32_t a1, uint32_t a2, uint32_t a3,
                                            uint32_t b0, uint32_t b1) {
    asm volatile(
        "mma.sync.aligned.m16n8k8.row.col.f32.tf32.tf32.f32 "
        "{%0,%1,%2,%3}, {%4,%5,%6,%7}, {%8,%9}, {%0,%1,%2,%3};"
        : "+f"(d0), "+f"(d1), "+f"(d2), "+f"(d3)
        : "r"(a0), "r"(a1), "r"(a2), "r"(a3), "r"(b0), "r"(b1));
}

// L1-bypassing (gpu-scope) loads/stores for the producer-consumer handoff
static __device__ __forceinline__ float4 ld_rlx4(const float* p) {
    float4 v;
    asm volatile("ld.relaxed.gpu.global.v4.f32 {%0,%1,%2,%3}, [%4];"
                 : "=f"(v.x), "=f"(v.y), "=f"(v.z), "=f"(v.w) : "l"(p) : "memory");
    return v;
}
static __device__ __forceinline__ void st_rlx(float* p, float v) {
    asm volatile("st.relaxed.gpu.global.f32 [%0], %1;" :: "l"(p), "f"(v) : "memory");
}
static __device__ __forceinline__ bool has_sent(float4 v) {
    return (__float_as_uint(v.x) == SENT) | (__float_as_uint(v.y) == SENT) |
           (__float_as_uint(v.z) == SENT) | (__float_as_uint(v.w) == SENT);
}

// fill g_hstage with the sentinel pattern (runs first, every launch)
__global__ void fill_sentinel_kernel() {
    const size_t n4 = (size_t)2 * TT * HH * BB / 4;
    uint4 s = make_uint4(SENT, SENT, SENT, SENT);
    uint4* p = reinterpret_cast<uint4*>(g_hstage);
    for (size_t i = blockIdx.x * (size_t)blockDim.x + threadIdx.x; i < n4;
         i += (size_t)gridDim.x * blockDim.x)
        p[i] = s;
}

// ---------------------------------------------------------------------------
// Phase 1: pre-gates = x @ W_x^T + bias, both directions (tf32 mma GEMM).
// M = 8192, N = 1536, K = 1024. CTA tile 128x128x32, 8 warps, warp 64x32.
// ---------------------------------------------------------------------------
__global__ __launch_bounds__(256) void pregemm_kernel(
    const float* __restrict__ x,
    const float* __restrict__ wf, const float* __restrict__ bf,
    const float* __restrict__ wb, const float* __restrict__ bb) {
    const int d = blockIdx.z;
    const float* __restrict__ w    = d ? wb : wf;
    const float* __restrict__ bias = d ? bb : bf;
    const int row0 = blockIdx.y * 128;
    const int col0 = blockIdx.x * 128;

    __shared__ float As[128][36];
    __shared__ float Bs[128][36];

    const int tid = threadIdx.x;
    const int lane = tid & 31, wid = tid >> 5;
    const int wm = wid >> 2, wn = wid & 3;
    const int g = lane >> 2, t4 = lane & 3;

    float acc[4][4][4];
#pragma unroll
    for (int i = 0; i < 4; i++)
#pragma unroll
        for (int j = 0; j < 4; j++)
#pragma unroll
            for (int r = 0; r < 4; r++) acc[i][j][r] = 0.f;

    for (int k0 = 0; k0 < EE; k0 += 32) {
#pragma unroll
        for (int i = 0; i < 4; i++) {
            int idx = tid + i * 256;
            int m = idx >> 3, kq = idx & 7;
            int row = row0 + m;
            int t = row >> 4, b = row & 15;
            float4 v = *reinterpret_cast<const float4*>(
                x + (size_t)(b * TT + t) * EE + k0 + kq * 4);
            float4 o = make_float4(f2tff(v.x), f2tff(v.y), f2tff(v.z), f2tff(v.w));
            *reinterpret_cast<float4*>(&As[m][kq * 4]) = o;
        }
#pragma unroll
        for (int i = 0; i < 4; i++) {
            int idx = tid + i * 256;
            int n = idx >> 3, kq = idx & 7;
            float4 v = *reinterpret_cast<const float4*>(
                w + (size_t)(col0 + n) * G3 + k0 + kq * 4);
            float4 o = make_float4(f2tff(v.x), f2tff(v.y), f2tff(v.z), f2tff(v.w));
            *reinterpret_cast<float4*>(&Bs[n][kq * 4]) = o;
        }
        __syncthreads();

#pragma unroll
        for (int kt = 0; kt < 4; kt++) {
            int k = kt * 8;
            uint32_t a[4][4];
#pragma unroll
            for (int mt = 0; mt < 4; mt++) {
                int mb = wm * 64 + mt * 16;
                a[mt][0] = __float_as_uint(As[mb + g][k + t4]);
                a[mt][1] = __float_as_uint(As[mb + g + 8][k + t4]);
                a[mt][2] = __float_as_uint(As[mb + g][k + 4 + t4]);
                a[mt][3] = __float_as_uint(As[mb + g + 8][k + 4 + t4]);
            }
#pragma unroll
            for (int nt = 0; nt < 4; nt++) {
                int nb = wn * 32 + nt * 8;
                uint32_t b0 = __float_as_uint(Bs[nb + g][k + t4]);
                uint32_t b1 = __float_as_uint(Bs[nb + g][k + 4 + t4]);
#pragma unroll
                for (int mt = 0; mt < 4; mt++)
                    mma8(acc[mt][nt][0], acc[mt][nt][1], acc[mt][nt][2], acc[mt][nt][3],
                         a[mt][0], a[mt][1], a[mt][2], a[mt][3], b0, b1);
            }
        }
        __syncthreads();
    }

#pragma unroll
    for (int mt = 0; mt < 4; mt++) {
        int rowb = row0 + wm * 64 + mt * 16 + g;
#pragma unroll
        for (int nt = 0; nt < 4; nt++) {
            int colb = col0 + wn * 32 + nt * 8 + 2 * t4;
#pragma unroll
            for (int r = 0; r < 4; r++) {
                int row = rowb + ((r >= 2) ? 8 : 0);
                int col = colb + (r & 1);
                int t = row >> 4, b = row & 15;
                float v = acc[mt][nt][r] + __ldg(bias + col);
                g_preg[(((size_t)d * TT + t) * G3 + col) * BB + b] = v;
            }
        }
    }
}

// ---------------------------------------------------------------------------
// Phase 2: persistent recurrence — R10 structure (warp-owned 128B hst lines,
// coalesced publish, cheap 16B spin) with two refinements:
//  (1) opportunistic first probe: iteration 0 loads the full line; if the
//      data is already there the handoff is ONE L2 RT; otherwise fall back
//      to the cheap 16B spin + one-shot verify (no traffic storm).
//  (2) the deferred `out` write moves to idle warps 4-7.
// ---------------------------------------------------------------------------
#define WPAD 516
#define RPAD 25

__global__ __launch_bounds__(256) void recur_kernel(
    const float* __restrict__ wf, const float* __restrict__ wb,
    const float* __restrict__ h0f, const float* __restrict__ h0b,
    const float* __restrict__ c0f, const float* __restrict__ c0b,
    float* __restrict__ out) {
    extern __shared__ float sm[];
    float* hsm = sm;                       // 16 x WPAD  (h_{t-1} [b][k])
    float* red = sm + 16 * WPAD;           // 2 x 8 x 16 x RPAD (parity)
    float* hT  = red + 2 * 8 * 16 * RPAD;  // 2 x 8 x 20 parity h buffer

    const int d   = (int)blockIdx.x >> 6;
    const int grp = (int)blockIdx.x & 63;
    const int n0  = grp * 8;
    const float* __restrict__ w  = d ? wb : wf;
    const float* __restrict__ h0 = d ? h0b : h0f;
    const float* __restrict__ c0 = d ? c0b : c0f;
    const float* __restrict__ preg = g_preg + (size_t)d * TT * G3 * BB;
    float* __restrict__ hst = g_hstage + (size_t)d * TT * HH * BB;

    const int tid = threadIdx.x, lane = tid & 31, wid = tid >> 5;
    const int g = lane >> 2, t4 = lane & 3;
    // epilogue mapping: warp w owns cols 2w,2w+1 x all 16 batches
    const int eb = tid & 15, en = (tid >> 4) & 7;
    // out-writeback mapping for warps 4-7 (coalesced)
    const int en2 = tid & 7, eb2 = (tid >> 3) & 15;
    const bool epi = tid < 128;
    const bool outw = tid >= 128;     // warps 4-7 handle deferred out writes
    const int kbase = wid * 64;       // this warp's K slice
    const int k2 = tid * 2;           // the 2 k-columns I stage (one 128B line)

    // Preload this thread's W_h B-fragments into registers (tf32).
    float breg[8][3][2];
#pragma unroll
    for (int nt = 0; nt < 3; nt++) {
        const float* wr = w + (size_t)(nt * 512 + n0 + g) * G3 + 1024;
#pragma unroll
        for (int kt = 0; kt < 8; kt++) {
            int col = kbase + kt * 8;
            breg[kt][nt][0] = f2tff(__ldg(wr + col + t4));
            breg[kt][nt][1] = f2tff(__ldg(wr + col + 4 + t4));
        }
    }
    float c = epi ? c0[n0 + en] : 0.f;  // cell state in a register

    // step-0 h: broadcast h0 over batch into my 2 columns
    {
        float2 o = make_float2(f2tff(h0[k2]), f2tff(h0[k2 + 1]));
#pragma unroll
        for (int b = 0; b < 16; b++)
            *reinterpret_cast<float2*>(&hsm[b * WPAD + k2]) = o;
    }
    __syncthreads();

    for (int s = 0; s < TT; s++) {
        const int tt = d ? (TT - 1 - s) : s;
        const int par = s & 1;
        float* redp = red + par * (8 * 16 * RPAD);

        // pre-gate prefetch (independent; overlaps the poll below)
        float pgi = 0.f, pgj = 0.f, pgo = 0.f;
        if (epi) {
            pgi = __ldg(preg + ((size_t)tt * G3 + (n0 + en)) * BB + eb);
            pgj = __ldg(preg + ((size_t)tt * G3 + (512 + n0 + en)) * BB + eb);
            pgo = __ldg(preg + ((size_t)tt * G3 + (1024 + n0 + en)) * BB + eb);
        }

        if (s > 0) {
            const int tp = d ? (tt + 1) : (tt - 1);
            const float* sp = hst + ((size_t)tp * HH + k2) * BB;
            float4 v[8];
            // opportunistic first probe: full line in one shot
            bool bad = false;
#pragma unroll
            for (int q = 0; q < 8; q++) {
                v[q] = ld_rlx4(sp + q * 4);
                bad |= has_sent(v[q]);
            }
            while (bad) {
                // cheap 16B spin until arrival, then one-shot verify
                do { v[0] = ld_rlx4(sp); } while (has_sent(v[0]));
                bad = false;
#pragma unroll
                for (int q = 1; q < 8; q++) {
                    v[q] = ld_rlx4(sp + q * 4);
                    bad |= has_sent(v[q]);
                }
            }
            // transpose: v[0..3] = col k2 (b 0..15), v[4..7] = col k2+1
#pragma unroll
            for (int q = 0; q < 4; q++) {
                const float* a = &v[q].x;
                const float* bq = &v[4 + q].x;
#pragma unroll
                for (int r = 0; r < 4; r++)
                    *reinterpret_cast<float2*>(&hsm[(q * 4 + r) * WPAD + k2]) =
                        make_float2(a[r], bq[r]);
            }
        }
        __syncwarp();  // my warp's staging visible to my warp's mma

        // per-warp mma on its own K slice: A from SMEM, B from registers
        float acc[3][4];
#pragma unroll
        for (int nt = 0; nt < 3; nt++)
#pragma unroll
            for (int r = 0; r < 4; r++) acc[nt][r] = 0.f;

#pragma unroll
        for (int kt = 0; kt < 8; kt++) {
            int k = kbase + kt * 8;
            uint32_t a0 = __float_as_uint(hsm[g * WPAD + k + t4]);
            uint32_t a1 = __float_as_uint(hsm[(g + 8) * WPAD + k + t4]);
            uint32_t a2 = __float_as_uint(hsm[g * WPAD + k + 4 + t4]);
            uint32_t a3 = __float_as_uint(hsm[(g + 8) * WPAD + k + 4 + t4]);
#pragma unroll
            for (int nt = 0; nt < 3; nt++)
                mma8(acc[nt][0], acc[nt][1], acc[nt][2], acc[nt][3],
                     a0, a1, a2, a3,
                     __float_as_uint(breg[kt][nt][0]),
                     __float_as_uint(breg[kt][nt][1]));
        }

        // cross-warp K reduction via SMEM (parity-buffered)
        float* rw = redp + wid * 16 * RPAD;
#pragma unroll
        for (int nt = 0; nt < 3; nt++) {
            int rl = nt * 8 + 2 * t4;
            rw[g * RPAD + rl]           = acc[nt][0];
            rw[g * RPAD + rl + 1]       = acc[nt][1];
            rw[(g + 8) * RPAD + rl]     = acc[nt][2];
            rw[(g + 8) * RPAD + rl + 1] = acc[nt][3];
        }
        __syncthreads();  // the single CTA-wide barrier per step

        if (epi) {
            float si = pgi, sj = pgj, so = pgo;
#pragma unroll
            for (int wq = 0; wq < 8; wq++) {
                const float* rr = redp + (wq * 16 + eb) * RPAD;
                si += rr[en];
                sj += rr[8 + en];
                so += rr[16 + en];
            }
            // fast MUFU-only gates (err ~1e-6)
            float ig = rcpa(1.f + __expf(-si));
            float tj = 1.f - 2.f * rcpa(1.f + __expf(2.f * sj));
            c = (1.f - ig) * c + ig * tj;                       // coupled gate
            float tc = 1.f - 2.f * rcpa(1.f + __expf(2.f * c));
            float h = tc * rcpa(1.f + __expf(-so));

            // publish FIRST: my warp owns one full 128B hst line -> one
            // coalesced wavefront, atomic-ish arrival at L2
            st_rlx(hst + ((size_t)tt * HH + n0 + en) * BB + eb, f2tff(h));
            // stash full-precision h for the deferred out write
            hT[par * 160 + en * 20 + eb] = h;
        } else if (outw && s > 0) {
            // warps 4-7: deferred coalesced out write for step s-1
            // (hT[par^1] was written post-barrier in step s-1; this step's
            // __syncthreads orders it before these reads)
            const float* hTp = hT + (par ^ 1) * 160;
            const int tprev = d ? (TT - s) : (s - 1);
            out[(size_t)(eb2 * TT + tprev) * 1024 + d * 512 + n0 + en2] =
                hTp[en2 * 20 + eb2];
        }
    }

    // flush the final step's out values
    __syncthreads();
    if (outw) {
        const float* hTp = hT + ((TT - 1) & 1) * 160;
        const int tlast = d ? 0 : (TT - 1);
        out[(size_t)(eb2 * TT + tlast) * 1024 + d * 512 + n0 + en2] =
            hTp[en2 * 20 + eb2];
    }
}

extern "C" void kernel_launch(void* const* d_in, const int* in_sizes, int n_in,
                              void* d_out, int out_size) {
    (void)in_sizes; (void)n_in; (void)out_size;
    const float* x   = (const float*)d_in[0];
    const float* wf  = (const float*)d_in[1];
    const float* bf  = (const float*)d_in[2];
    const float* wb  = (const float*)d_in[3];
    const float* bb  = (const float*)d_in[4];
    const float* h0f = (const float*)d_in[5];
    const float* h0b = (const float*)d_in[6];
    const float* c0f = (const float*)d_in[7];
    const float* c0b = (const float*)d_in[8];
    float* out = (float*)d_out;

    const int rsm_bytes = (16 * WPAD + 2 * 8 * 16 * RPAD + 2 * 160) * 4;  // 59904
    cudaFuncSetAttribute(recur_kernel, cudaFuncAttributeMaxDynamicSharedMemorySize,
                         rsm_bytes);

    fill_sentinel_kernel<<<512, 256>>>();
    dim3 g1(G3 / 128, (TT * BB) / 128, 2);
    pregemm_kernel<<<g1, 256>>>(x, wf, bf, wb, bb);
    recur_kernel<<<128, 256, rsm_bytes>>>(wf, wb, h0f, h0b, c0f, c0b, out);
}

// round 13
// speedup vs baseline: 1.4241x; 1.2494x over previous
#include <cuda_runtime.h>
#include <cstdint>
#include <cstddef>

#define TT 512
#define BB 16
#define EE 1024
#define HH 512
#define G3 1536
#define SENT 0x7FC00001u

// pre-gate scratch [d][t][col][b]
__device__ float g_preg[(size_t)2 * TT * G3 * BB];
// tf32-pre-rounded h staging [d][t][k][b]; sentinel-filled each launch
__device__ float g_hstage[(size_t)2 * TT * HH * BB];
// tf32-pre-rounded GEMM inputs (written once per launch by convert kernel)
__device__ float g_xtf[(size_t)BB * TT * EE];
__device__ float g_wtf[2][(size_t)G3 * EE];

static __device__ __forceinline__ uint32_t f2tf(float f) {
    uint32_t r; asm("cvt.rna.tf32.f32 %0, %1;" : "=r"(r) : "f"(f)); return r;
}
static __device__ __forceinline__ float f2tff(float f) { return __uint_as_float(f2tf(f)); }
static __device__ __forceinline__ float rcpa(float x) {
    float r; asm("rcp.approx.f32 %0, %1;" : "=f"(r) : "f"(x)); return r;
}

static __device__ __forceinline__ void mma8(float& d0, float& d1, float& d2, float& d3,
                                            uint32_t a0, uint32_t a1, uint32_t a2, uint32_t a3,
                                            uint32_t b0, uint32_t b1) {
    asm volatile(
        "mma.sync.aligned.m16n8k8.row.col.f32.tf32.tf32.f32 "
        "{%0,%1,%2,%3}, {%4,%5,%6,%7}, {%8,%9}, {%0,%1,%2,%3};"
        : "+f"(d0), "+f"(d1), "+f"(d2), "+f"(d3)
        : "r"(a0), "r"(a1), "r"(a2), "r"(a3), "r"(b0), "r"(b1));
}

// L1-bypassing (gpu-scope) loads/stores for the producer-consumer handoff
static __device__ __forceinline__ float4 ld_rlx4(const float* p) {
    float4 v;
    asm volatile("ld.relaxed.gpu.global.v4.f32 {%0,%1,%2,%3}, [%4];"
                 : "=f"(v.x), "=f"(v.y), "=f"(v.z), "=f"(v.w) : "l"(p) : "memory");
    return v;
}
static __device__ __forceinline__ void st_rlx(float* p, float v) {
    asm volatile("st.relaxed.gpu.global.f32 [%0], %1;" :: "l"(p), "f"(v) : "memory");
}
static __device__ __forceinline__ bool has_sent(float4 v) {
    return (__float_as_uint(v.x) == SENT) | (__float_as_uint(v.y) == SENT) |
           (__float_as_uint(v.z) == SENT) | (__float_as_uint(v.w) == SENT);
}

static __device__ __forceinline__ void cp_async16(uint32_t smem_addr, const void* gptr) {
    asm volatile("cp.async.ca.shared.global [%0], [%1], 16;"
                 :: "r"(smem_addr), "l"(gptr) : "memory");
}

// fill g_hstage with the sentinel pattern (runs first, every launch)
__global__ void fill_sentinel_kernel() {
    const size_t n4 = (size_t)2 * TT * HH * BB / 4;
    uint4 s = make_uint4(SENT, SENT, SENT, SENT);
    uint4* p = reinterpret_cast<uint4*>(g_hstage);
    for (size_t i = blockIdx.x * (size_t)blockDim.x + threadIdx.x; i < n4;
         i += (size_t)gridDim.x * blockDim.x)
        p[i] = s;
}

// pre-round x and the first EE columns of both W's to tf32 (once per launch)
__global__ void convert_tf32_kernel(const float* __restrict__ x,
                                    const float* __restrict__ wf,
                                    const float* __restrict__ wb) {
    const size_t stride = (size_t)gridDim.x * blockDim.x;
    const size_t base = blockIdx.x * (size_t)blockDim.x + threadIdx.x;
    // x: straight copy with rounding (layout preserved)
    const size_t nx4 = (size_t)BB * TT * EE / 4;
    for (size_t i = base; i < nx4; i += stride) {
        float4 v = reinterpret_cast<const float4*>(x)[i];
        reinterpret_cast<float4*>(g_xtf)[i] =
            make_float4(f2tff(v.x), f2tff(v.y), f2tff(v.z), f2tff(v.w));
    }
    // W: gather cols [0,EE) of each G3-wide row into an EE-wide packed row
    const size_t nw4 = (size_t)G3 * EE / 4;
    for (size_t i = base; i < nw4; i += stride) {
        size_t r = i / (EE / 4), cq = i % (EE / 4);
        float4 vf = *reinterpret_cast<const float4*>(wf + r * G3 + cq * 4);
        float4 vb = *reinterpret_cast<const float4*>(wb + r * G3 + cq * 4);
        reinterpret_cast<float4*>(g_wtf[0])[i] =
            make_float4(f2tff(vf.x), f2tff(vf.y), f2tff(vf.z), f2tff(vf.w));
        reinterpret_cast<float4*>(g_wtf[1])[i] =
            make_float4(f2tff(vb.x), f2tff(vb.y), f2tff(vb.z), f2tff(vb.w));
    }
}

// ---------------------------------------------------------------------------
// Phase 1: pre-gates = x @ W_x^T + bias, both directions (tf32 mma GEMM).
// M = 8192, N = 1536, K = 1024. CTA tile 128x128x32, 8 warps, warp 64x32.
// cp.async 2-stage pipeline on pre-rounded tf32 inputs: copy(kb+1) overlaps
// mma(kb); zero register staging (the R7 spill trap); ONE barrier per chunk.
// ---------------------------------------------------------------------------
#define PT (128 * 36)

__global__ __launch_bounds__(256) void pregemm_kernel(
    const float* __restrict__ bf, const float* __restrict__ bb) {
    extern __shared__ float psm[];  // [2][ A(128*36) | B(128*36) ]
    const int d = blockIdx.z;
    const float* __restrict__ wtf  = g_wtf[d];
    const float* __restrict__ bias = d ? bb : bf;
    const int row0 = blockIdx.y * 128;
    const int col0 = blockIdx.x * 128;

    const int tid = threadIdx.x;
    const int lane = tid & 31, wid = tid >> 5;
    const int wm = wid >> 2, wn = wid & 3;
    const int g = lane >> 2, t4 = lane & 3;

    // copy coords: thread handles 4 A-chunks + 4 B-chunks of 16B each
    const int cm = tid >> 3;          // row within tile (+32*i)
    const int ckq = (tid & 7) * 4;    // float offset within the 32-float k-run

    float acc[4][4][4];
#pragma unroll
    for (int i = 0; i < 4; i++)
#pragma unroll
        for (int j = 0; j < 4; j++)
#pragma unroll
            for (int r = 0; r < 4; r++) acc[i][j][r] = 0.f;

    auto issue_stage = [&](int st, int k0) {
        float* As = psm + st * 2 * PT;
        float* Bs = As + PT;
#pragma unroll
        for (int i = 0; i < 4; i++) {
            int m = cm + i * 32;
            int row = row0 + m;
            int t = row >> 4, b = row & 15;
            cp_async16((uint32_t)__cvta_generic_to_shared(&As[m * 36 + ckq]),
                       g_xtf + (size_t)(b * TT + t) * EE + k0 + ckq);
            cp_async16((uint32_t)__cvta_generic_to_shared(&Bs[m * 36 + ckq]),
                       wtf + (size_t)(col0 + m) * EE + k0 + ckq);
        }
        asm volatile("cp.async.commit_group;" ::: "memory");
    };

    issue_stage(0, 0);

    for (int kb = 0; kb < 32; kb++) {
        asm volatile("cp.async.wait_group 0;" ::: "memory");
        __syncthreads();  // stage kb ready; all mma(kb-1) complete
        if (kb < 31) issue_stage((kb + 1) & 1, (kb + 1) * 32);

        const float* As = psm + (kb & 1) * 2 * PT;
        const float* Bs = As + PT;
#pragma unroll
        for (int kt = 0; kt < 4; kt++) {
            int k = kt * 8;
            uint32_t a[4][4];
#pragma unroll
            for (int mt = 0; mt < 4; mt++) {
                int mb = wm * 64 + mt * 16;
                a[mt][0] = __float_as_uint(As[(mb + g) * 36 + k + t4]);
                a[mt][1] = __float_as_uint(As[(mb + g + 8) * 36 + k + t4]);
                a[mt][2] = __float_as_uint(As[(mb + g) * 36 + k + 4 + t4]);
                a[mt][3] = __float_as_uint(As[(mb + g + 8) * 36 + k + 4 + t4]);
            }
#pragma unroll
            for (int nt = 0; nt < 4; nt++) {
                int nb = wn * 32 + nt * 8;
                uint32_t b0 = __float_as_uint(Bs[(nb + g) * 36 + k + t4]);
                uint32_t b1 = __float_as_uint(Bs[(nb + g) * 36 + k + 4 + t4]);
#pragma unroll
                for (int mt = 0; mt < 4; mt++)
                    mma8(acc[mt][nt][0], acc[mt][nt][1], acc[mt][nt][2], acc[mt][nt][3],
                         a[mt][0], a[mt][1], a[mt][2], a[mt][3], b0, b1);
            }
        }
    }

#pragma unroll
    for (int mt = 0; mt < 4; mt++) {
        int rowb = row0 + wm * 64 + mt * 16 + g;
#pragma unroll
        for (int nt = 0; nt < 4; nt++) {
            int colb = col0 + wn * 32 + nt * 8 + 2 * t4;
#pragma unroll
            for (int r = 0; r < 4; r++) {
                int row = rowb + ((r >= 2) ? 8 : 0);
                int col = colb + (r & 1);
                int t = row >> 4, b = row & 15;
                float v = acc[mt][nt][r] + __ldg(bias + col);
                g_preg[(((size_t)d * TT + t) * G3 + col) * BB + b] = v;
            }
        }
    }
}

// ---------------------------------------------------------------------------
// Phase 2: persistent recurrence — byte-exact R10 (best config, 1772us):
// warp-owned 128B hst lines, coalesced single-wavefront publish, cheap 16B
// detect spin + one-shot verify, deferred coalesced out write by epi warps.
// ---------------------------------------------------------------------------
#define WPAD 516
#define RPAD 25

__global__ __launch_bounds__(256) void recur_kernel(
    const float* __restrict__ wf, const float* __restrict__ wb,
    const float* __restrict__ h0f, const float* __restrict__ h0b,
    const float* __restrict__ c0f, const float* __restrict__ c0b,
    float* __restrict__ out) {
    extern __shared__ float sm[];
    float* hsm = sm;                       // 16 x WPAD  (h_{t-1} [b][k])
    float* red = sm + 16 * WPAD;           // 2 x 8 x 16 x RPAD (parity)
    float* hT  = red + 2 * 8 * 16 * RPAD;  // 2 x 8 x 20 parity h buffer

    const int d   = (int)blockIdx.x >> 6;
    const int grp = (int)blockIdx.x & 63;
    const int n0  = grp * 8;
    const float* __restrict__ w  = d ? wb : wf;
    const float* __restrict__ h0 = d ? h0b : h0f;
    const float* __restrict__ c0 = d ? c0b : c0f;
    const float* __restrict__ preg = g_preg + (size_t)d * TT * G3 * BB;
    float* __restrict__ hst = g_hstage + (size_t)d * TT * HH * BB;

    const int tid = threadIdx.x, lane = tid & 31, wid = tid >> 5;
    const int g = lane >> 2, t4 = lane & 3;
    // epilogue mapping: warp w owns cols 2w,2w+1 x all 16 batches
    const int eb = tid & 15, en = (tid >> 4) & 7;
    // out-writeback mapping (coalesced): consecutive lanes -> consecutive cols
    const int en2 = tid & 7, eb2 = (tid >> 3) & 15;
    const bool epi = tid < 128;
    const int kbase = wid * 64;       // this warp's K slice
    const int k2 = tid * 2;           // the 2 k-columns I stage (one 128B line)

    // Preload this thread's W_h B-fragments into registers (tf32).
    float breg[8][3][2];
#pragma unroll
    for (int nt = 0; nt < 3; nt++) {
        const float* wr = w + (size_t)(nt * 512 + n0 + g) * G3 + 1024;
#pragma unroll
        for (int kt = 0; kt < 8; kt++) {
            int col = kbase + kt * 8;
            breg[kt][nt][0] = f2tff(__ldg(wr + col + t4));
            breg[kt][nt][1] = f2tff(__ldg(wr + col + 4 + t4));
        }
    }
    float c = epi ? c0[n0 + en] : 0.f;  // cell state in a register

    // step-0 h: broadcast h0 over batch into my 2 columns
    {
        float2 o = make_float2(f2tff(h0[k2]), f2tff(h0[k2 + 1]));
#pragma unroll
        for (int b = 0; b < 16; b++)
            *reinterpret_cast<float2*>(&hsm[b * WPAD + k2]) = o;
    }
    __syncthreads();

    for (int s = 0; s < TT; s++) {
        const int tt = d ? (TT - 1 - s) : s;
        const int par = s & 1;
        float* redp = red + par * (8 * 16 * RPAD);

        // pre-gate prefetch (independent; overlaps the poll below)
        float pgi = 0.f, pgj = 0.f, pgo = 0.f;
        if (epi) {
            pgi = __ldg(preg + ((size_t)tt * G3 + (n0 + en)) * BB + eb);
            pgj = __ldg(preg + ((size_t)tt * G3 + (512 + n0 + en)) * BB + eb);
            pgo = __ldg(preg + ((size_t)tt * G3 + (1024 + n0 + en)) * BB + eb);
        }

        if (s > 0) {
            // poll MY line (data-as-flag): spin on first 16B, then verify all
            const int tp = d ? (tt + 1) : (tt - 1);
            const float* sp = hst + ((size_t)tp * HH + k2) * BB;
            float4 v[8];
            do { v[0] = ld_rlx4(sp); } while (has_sent(v[0]));
            for (;;) {
                bool bad = false;
#pragma unroll
                for (int q = 1; q < 8; q++) {
                    v[q] = ld_rlx4(sp + q * 4);
                    bad |= has_sent(v[q]);
                }
                if (!bad) break;
            }
            // transpose: v[0..3] = col k2 (b 0..15), v[4..7] = col k2+1
#pragma unroll
            for (int q = 0; q < 4; q++) {
                const float* a = &v[q].x;
                const float* bq = &v[4 + q].x;
#pragma unroll
                for (int r = 0; r < 4; r++)
                    *reinterpret_cast<float2*>(&hsm[(q * 4 + r) * WPAD + k2]) =
                        make_float2(a[r], bq[r]);
            }
        }
        __syncwarp();  // my warp's staging visible to my warp's mma

        // per-warp mma on its own K slice: A from SMEM, B from registers
        float acc[3][4];
#pragma unroll
        for (int nt = 0; nt < 3; nt++)
#pragma unroll
            for (int r = 0; r < 4; r++) acc[nt][r] = 0.f;

#pragma unroll
        for (int kt = 0; kt < 8; kt++) {
            int k = kbase + kt * 8;
            uint32_t a0 = __float_as_uint(hsm[g * WPAD + k + t4]);
            uint32_t a1 = __float_as_uint(hsm[(g + 8) * WPAD + k + t4]);
            uint32_t a2 = __float_as_uint(hsm[g * WPAD + k + 4 + t4]);
            uint32_t a3 = __float_as_uint(hsm[(g + 8) * WPAD + k + 4 + t4]);
#pragma unroll
            for (int nt = 0; nt < 3; nt++)
                mma8(acc[nt][0], acc[nt][1], acc[nt][2], acc[nt][3],
                     a0, a1, a2, a3,
                     __float_as_uint(breg[kt][nt][0]),
                     __float_as_uint(breg[kt][nt][1]));
        }

        // cross-warp K reduction via SMEM (parity-buffered)
        float* rw = redp + wid * 16 * RPAD;
#pragma unroll
        for (int nt = 0; nt < 3; nt++) {
            int rl = nt * 8 + 2 * t4;
            rw[g * RPAD + rl]           = acc[nt][0];
            rw[g * RPAD + rl + 1]       = acc[nt][1];
            rw[(g + 8) * RPAD + rl]     = acc[nt][2];
            rw[(g + 8) * RPAD + rl + 1] = acc[nt][3];
        }
        __syncthreads();  // the single CTA-wide barrier per step

        if (epi) {
            float si = pgi, sj = pgj, so = pgo;
#pragma unroll
            for (int wq = 0; wq < 8; wq++) {
                const float* rr = redp + (wq * 16 + eb) * RPAD;
                si += rr[en];
                sj += rr[8 + en];
                so += rr[16 + en];
            }
            // fast MUFU-only gates (err ~1e-6)
            float ig = rcpa(1.f + __expf(-si));
            float tj = 1.f - 2.f * rcpa(1.f + __expf(2.f * sj));
            c = (1.f - ig) * c + ig * tj;                       // coupled gate
            float tc = 1.f - 2.f * rcpa(1.f + __expf(2.f * c));
            float h = tc * rcpa(1.f + __expf(-so));

            // publish FIRST: my warp owns one full 128B hst line -> one
            // coalesced wavefront, atomic-ish arrival at L2
            st_rlx(hst + ((size_t)tt * HH + n0 + en) * BB + eb, f2tff(h));
            // stash full-precision h for the deferred out write
            hT[par * 160 + en * 20 + eb] = h;

            // deferred coalesced out write for step s-1 (off critical path)
            if (s > 0) {
                const float* hTp = hT + (par ^ 1) * 160;
                const int tprev = d ? (TT - s) : (s - 1);
                out[(size_t)(eb2 * TT + tprev) * 1024 + d * 512 + n0 + en2] =
                    hTp[en2 * 20 + eb2];
            }
        }
    }

    // flush the final step's out values
    __syncthreads();
    if (epi) {
        const float* hTp = hT + ((TT - 1) & 1) * 160;
        const int tlast = d ? 0 : (TT - 1);
        out[(size_t)(eb2 * TT + tlast) * 1024 + d * 512 + n0 + en2] =
            hTp[en2 * 20 + eb2];
    }
}

extern "C" void kernel_launch(void* const* d_in, const int* in_sizes, int n_in,
                              void* d_out, int out_size) {
    (void)in_sizes; (void)n_in; (void)out_size;
    const float* x   = (const float*)d_in[0];
    const float* wf  = (const float*)d_in[1];
    const float* bf  = (const float*)d_in[2];
    const float* wb  = (const float*)d_in[3];
    const float* bb  = (const float*)d_in[4];
    const float* h0f = (const float*)d_in[5];
    const float* h0b = (const float*)d_in[6];
    const float* c0f = (const float*)d_in[7];
    const float* c0b = (const float*)d_in[8];
    float* out = (float*)d_out;

    const int psm_bytes = 4 * PT * 4;  // 73728 (2 stages x (A|B))
    cudaFuncSetAttribute(pregemm_kernel, cudaFuncAttributeMaxDynamicSharedMemorySize,
                         psm_bytes);
    const int rsm_bytes = (16 * WPAD + 2 * 8 * 16 * RPAD + 2 * 160) * 4;  // 59904
    cudaFuncSetAttribute(recur_kernel, cudaFuncAttributeMaxDynamicSharedMemorySize,
                         rsm_bytes);

    fill_sentinel_kernel<<<512, 256>>>();
    convert_tf32_kernel<<<512, 256>>>(x, wf, wb);
    dim3 g1(G3 / 128, (TT * BB) / 128, 2);
    pregemm_kernel<<<g1, 256, psm_bytes>>>(bf, bb);
    recur_kernel<<<128, 256, rsm_bytes>>>(wf, wb, h0f, h0b, c0f, c0b, out);
}